// round 9
// baseline (speedup 1.0000x reference)
#include <cuda_runtime.h>
#include <cstdint>

#define B_ 8
#define S_ 2048
#define H_ 1024
#define M_ (B_ * S_)   // 16384

// Scratch (static __device__ — allocation-free per harness rules)
static __device__ float g_Q[(size_t)B_ * S_ * H_];    // 64 MB (tf32-rounded)
static __device__ float g_K[(size_t)B_ * S_ * H_];    // 64 MB (tf32-rounded)
static __device__ float g_V[(size_t)B_ * S_ * H_];    // 64 MB (tf32-rounded)
static __device__ float g_P[(size_t)B_ * S_ * S_];    // 128 MB (scores fp32 -> probs tf32)
static __device__ float g_d1[(size_t)B_ * S_];
static __device__ float g_HS[(size_t)B_ * S_ * H_];   // 64 MB tf32-rounded hidden_states
static __device__ float g_W[(size_t)3 * H_ * H_];     // 12 MB tf32-rounded Wq|Wk|Wv

// ---------------------------------------------------------------------------
// TF32 / cp.async helpers
// ---------------------------------------------------------------------------
__device__ __forceinline__ uint32_t f2tf(float x) {
    uint32_t u;
    asm("cvt.rna.tf32.f32 %0, %1;" : "=r"(u) : "f"(x));
    return u;
}

__device__ __forceinline__ void mma_tf32(float c[4], const uint32_t a[4], const uint32_t b[2]) {
    asm volatile(
        "mma.sync.aligned.m16n8k8.row.col.f32.tf32.tf32.f32 "
        "{%0,%1,%2,%3}, {%4,%5,%6,%7}, {%8,%9}, {%0,%1,%2,%3};"
        : "+f"(c[0]), "+f"(c[1]), "+f"(c[2]), "+f"(c[3])
        : "r"(a[0]), "r"(a[1]), "r"(a[2]), "r"(a[3]), "r"(b[0]), "r"(b[1]));
}

__device__ __forceinline__ void cp_async16(uint32_t smem_dst, const void* gsrc) {
    asm volatile("cp.async.cg.shared.global [%0], [%1], 16;\n" :: "r"(smem_dst), "l"(gsrc));
}
__device__ __forceinline__ void cp_commit() {
    asm volatile("cp.async.commit_group;\n" ::: "memory");
}
__device__ __forceinline__ void cp_wait1() {
    asm volatile("cp.async.wait_group 1;\n" ::: "memory");
}
__device__ __forceinline__ void cp_wait0() {
    asm volatile("cp.async.wait_group 0;\n" ::: "memory");
}

// ---------------------------------------------------------------------------
// Elementwise tf32 pre-round: dst[i] = round_tf32(src[i])
// ---------------------------------------------------------------------------
__global__ __launch_bounds__(256) void round_tf32_kernel(
    const float* __restrict__ src, float* __restrict__ dst)
{
    size_t i = ((size_t)blockIdx.x * 256 + threadIdx.x) * 4;
    float4 v = *(const float4*)(src + i);
    uint4 u = make_uint4(f2tf(v.x), f2tf(v.y), f2tf(v.z), f2tf(v.w));
    *(uint4*)(dst + i) = u;
}

// ---------------------------------------------------------------------------
// Pipelined GEMM mainloop (tf32 MMA, cp.async double buffer).
// C[128x128] tile = A[m0:,k] * B.  Inputs must be pre-rounded to tf32 bits.
//   BMODE 0: Bsrc is [N,K] row-major, staged as Bs[n][k] pitch 36
//   BMODE 1: Bsrc is [K,N] row-major, staged as Bs[k][n] pitch 136
// 256 threads = 8 warps (2x4); warp tile 64x32; mma m16n8k8.
// ---------------------------------------------------------------------------
#define APITCH 36
#define ASZ (128 * APITCH)            // uint32 per A buffer
#define BSZ0 (128 * 36)
#define BSZ1 (32 * 136)

template<int BMODE>
__device__ __forceinline__ void gemm_pipe(
    const float* __restrict__ A, int lda,
    const float* __restrict__ Bsrc, int ldb,
    int m0, int n0, int K,
    uint32_t* As, uint32_t* Bs,
    float acc[4][4][4])
{
    const int BSZ = (BMODE == 0) ? BSZ0 : BSZ1;
    const uint32_t As_s = (uint32_t)__cvta_generic_to_shared(As);
    const uint32_t Bs_s = (uint32_t)__cvta_generic_to_shared(Bs);

    const int tid  = threadIdx.x;
    const int lane = tid & 31;
    const int w    = tid >> 5;
    const int g    = lane >> 2;
    const int t    = lane & 3;
    const int wm   = (w >> 2) * 64;
    const int wn   = (w & 3)  * 32;

    // Per-thread staging coordinates (4 chunks of 16B each for A and B)
    const int ar = tid >> 3, ac = (tid & 7) * 4;          // +32 rows per chunk
    const int br1 = tid >> 5, bc1 = (tid & 31) * 4;       // BMODE1: +8 rows per chunk

    auto stage = [&](int buf, int k0) {
        #pragma unroll
        for (int p = 0; p < 4; p++) {
            int r = ar + p * 32;
            cp_async16(As_s + (uint32_t)(buf * ASZ + r * APITCH + ac) * 4,
                       A + (size_t)(m0 + r) * lda + k0 + ac);
        }
        if (BMODE == 0) {
            #pragma unroll
            for (int p = 0; p < 4; p++) {
                int r = ar + p * 32;
                cp_async16(Bs_s + (uint32_t)(buf * BSZ0 + r * 36 + ac) * 4,
                           Bsrc + (size_t)(n0 + r) * ldb + k0 + ac);
            }
        } else {
            #pragma unroll
            for (int p = 0; p < 4; p++) {
                int r = br1 + p * 8;
                cp_async16(Bs_s + (uint32_t)(buf * BSZ1 + r * 136 + bc1) * 4,
                           Bsrc + (size_t)(k0 + r) * ldb + n0 + bc1);
            }
        }
        cp_commit();
    };

    stage(0, 0);
    int buf = 0;
    for (int k0 = 0; k0 < K; k0 += 32) {
        if (k0 + 32 < K) { stage(buf ^ 1, k0 + 32); cp_wait1(); }
        else             { cp_wait0(); }
        __syncthreads();

        const uint32_t* Ab = As + buf * ASZ;
        const uint32_t* Bb = Bs + buf * BSZ;

        #pragma unroll
        for (int ks = 0; ks < 32; ks += 8) {
            uint32_t af[4][4], bf[4][2];
            #pragma unroll
            for (int mi = 0; mi < 4; mi++) {
                const uint32_t* ap = Ab + (wm + 16 * mi + g) * APITCH + ks + t;
                af[mi][0] = ap[0];
                af[mi][1] = ap[8 * APITCH];
                af[mi][2] = ap[4];
                af[mi][3] = ap[8 * APITCH + 4];
            }
            #pragma unroll
            for (int ni = 0; ni < 4; ni++) {
                if (BMODE == 0) {
                    const uint32_t* bp = Bb + (wn + 8 * ni + g) * 36 + ks + t;
                    bf[ni][0] = bp[0];
                    bf[ni][1] = bp[4];
                } else {
                    const uint32_t* bp = Bb + (ks + t) * 136 + wn + 8 * ni + g;
                    bf[ni][0] = bp[0];
                    bf[ni][1] = bp[4 * 136];
                }
            }
            #pragma unroll
            for (int mi = 0; mi < 4; mi++)
                #pragma unroll
                for (int ni = 0; ni < 4; ni++)
                    mma_tf32(acc[mi][ni], af[mi], bf[ni]);
        }
        __syncthreads();
        buf ^= 1;
    }
}

// Shared-memory footprints
#define SMEM_TN  ((2 * ASZ + 2 * BSZ0) * 4)   // 73728 B (qkv, scores)
#define SMEM_NN  ((2 * ASZ + 2 * BSZ1) * 4)   // 71680 B (ctx)

// ---------------------------------------------------------------------------
// Kernel 1: QKV projections.  C[M,N] = HS[M,K] @ W[N,K]^T + bias
// grid = (H/128, M/128, 3); writes tf32-rounded Q/K/V.
// ---------------------------------------------------------------------------
__global__ __launch_bounds__(256, 2) void qkv_gemm(
    const float* __restrict__ bq, const float* __restrict__ bk,
    const float* __restrict__ bv)
{
    extern __shared__ __align__(16) uint32_t smem[];
    uint32_t* As = smem;
    uint32_t* Bs = smem + 2 * ASZ;

    int z = blockIdx.z;
    const float* W = g_W + (size_t)z * H_ * H_;
    const float* bias = (z == 0) ? bq : (z == 1) ? bk : bv;
    float* out = (z == 0) ? g_Q : (z == 1) ? g_K : g_V;

    int m0 = blockIdx.y * 128, n0 = blockIdx.x * 128;
    float acc[4][4][4] = {};

    gemm_pipe<0>(g_HS, H_, W, H_, m0, n0, H_, As, Bs, acc);

    int lane = threadIdx.x & 31, w = threadIdx.x >> 5;
    int g = lane >> 2, t = lane & 3;
    int wm = (w >> 2) * 64, wn = (w & 3) * 32;

    #pragma unroll
    for (int mi = 0; mi < 4; mi++) {
        int row = m0 + wm + 16 * mi + g;
        #pragma unroll
        for (int ni = 0; ni < 4; ni++) {
            int col = n0 + wn + 8 * ni + 2 * t;
            float b0 = bias[col], b1 = bias[col + 1];
            uint2 lo = make_uint2(f2tf(acc[mi][ni][0] + b0), f2tf(acc[mi][ni][1] + b1));
            uint2 hi = make_uint2(f2tf(acc[mi][ni][2] + b0), f2tf(acc[mi][ni][3] + b1));
            *(uint2*)(out + (size_t)row * H_ + col)       = lo;
            *(uint2*)(out + (size_t)(row + 8) * H_ + col) = hi;
        }
    }
}

// ---------------------------------------------------------------------------
// Kernel 2: d1[b,q] = Q[b,q,:] . dist_emb[1,:]   (one warp per row)
// ---------------------------------------------------------------------------
__global__ __launch_bounds__(256) void d1_kernel(const float* __restrict__ dist)
{
    int row  = blockIdx.x * 8 + (threadIdx.x >> 5);
    int lane = threadIdx.x & 31;
    const float4* q4 = (const float4*)(g_Q + (size_t)row * H_);
    const float4* e4 = (const float4*)(dist + H_);   // row 1 of dist_emb
    float s = 0.f;
    #pragma unroll
    for (int i = lane; i < H_ / 4; i += 32) {
        float4 a = q4[i], b = e4[i];
        s += a.x * b.x + a.y * b.y + a.z * b.z + a.w * b.w;
    }
    #pragma unroll
    for (int o = 16; o; o >>= 1) s += __shfl_xor_sync(0xffffffffu, s, o);
    if (lane == 0) g_d1[row] = s;
}

// ---------------------------------------------------------------------------
// Kernel 3: scores per batch.  S = (Q @ K^T + d1*[rel==1]) / 32 + mask
// grid = (16, 16, B)
// ---------------------------------------------------------------------------
__global__ __launch_bounds__(256, 2) void scores_gemm(
    const int* __restrict__ rel, const float* __restrict__ mask)
{
    extern __shared__ __align__(16) uint32_t smem[];
    uint32_t* As = smem;
    uint32_t* Bs = smem + 2 * ASZ;

    int b = blockIdx.z;
    const float* A  = g_Q + (size_t)b * S_ * H_;
    const float* Bt = g_K + (size_t)b * S_ * H_;
    float* out         = g_P + (size_t)b * S_ * S_;
    const int* relb    = rel + (size_t)b * S_ * S_;
    const float* maskb = mask + (size_t)b * S_;

    int m0 = blockIdx.y * 128, n0 = blockIdx.x * 128;
    float acc[4][4][4] = {};

    gemm_pipe<0>(A, H_, Bt, H_, m0, n0, H_, As, Bs, acc);

    const float inv = 0.03125f;   // 1/sqrt(1024)
    int lane = threadIdx.x & 31, w = threadIdx.x >> 5;
    int g = lane >> 2, t = lane & 3;
    int wm = (w >> 2) * 64, wn = (w & 3) * 32;

    #pragma unroll
    for (int mi = 0; mi < 4; mi++) {
        int row = m0 + wm + 16 * mi + g;
        float dlo = g_d1[(size_t)b * S_ + row];
        float dhi = g_d1[(size_t)b * S_ + row + 8];
        #pragma unroll
        for (int ni = 0; ni < 4; ni++) {
            int col = n0 + wn + 8 * ni + 2 * t;
            float mk0 = maskb[col], mk1 = maskb[col + 1];
            int2 rlo = *(const int2*)(relb + (size_t)row * S_ + col);
            int2 rhi = *(const int2*)(relb + (size_t)(row + 8) * S_ + col);
            float o0 = (acc[mi][ni][0] + (rlo.x == 1 ? dlo : 0.f)) * inv + mk0;
            float o1 = (acc[mi][ni][1] + (rlo.y == 1 ? dlo : 0.f)) * inv + mk1;
            float o2 = (acc[mi][ni][2] + (rhi.x == 1 ? dhi : 0.f)) * inv + mk0;
            float o3 = (acc[mi][ni][3] + (rhi.y == 1 ? dhi : 0.f)) * inv + mk1;
            *(float2*)(out + (size_t)row * S_ + col)       = make_float2(o0, o1);
            *(float2*)(out + (size_t)(row + 8) * S_ + col) = make_float2(o2, o3);
        }
    }
}

// ---------------------------------------------------------------------------
// Kernel 4: row softmax over k (length 2048), in place on g_P.
// Writes tf32-rounded probs (same rounding the GEMM would apply anyway).
// ---------------------------------------------------------------------------
__global__ __launch_bounds__(256) void softmax_k()
{
    __shared__ float red[32];
    int row = blockIdx.x;
    float* p = g_P + (size_t)row * S_;
    int base = threadIdx.x * 8;

    float4 v0 = *(float4*)(p + base);
    float4 v1 = *(float4*)(p + base + 4);
    float x[8] = {v0.x,v0.y,v0.z,v0.w,v1.x,v1.y,v1.z,v1.w};

    float mx = x[0];
    #pragma unroll
    for (int i = 1; i < 8; i++) mx = fmaxf(mx, x[i]);
    #pragma unroll
    for (int o = 16; o; o >>= 1) mx = fmaxf(mx, __shfl_xor_sync(0xffffffffu, mx, o));
    int lane = threadIdx.x & 31, wid = threadIdx.x >> 5;
    if (lane == 0) red[wid] = mx;
    __syncthreads();
    if (wid == 0) {
        float m = (lane < 8) ? red[lane] : -1e30f;
        #pragma unroll
        for (int o = 4; o; o >>= 1) m = fmaxf(m, __shfl_xor_sync(0xffffffffu, m, o));
        if (lane == 0) red[0] = m;
    }
    __syncthreads();
    float m = red[0];

    float s = 0.f;
    #pragma unroll
    for (int i = 0; i < 8; i++) { x[i] = __expf(x[i] - m); s += x[i]; }
    #pragma unroll
    for (int o = 16; o; o >>= 1) s += __shfl_xor_sync(0xffffffffu, s, o);
    __syncthreads();
    if (lane == 0) red[wid] = s;
    __syncthreads();
    if (wid == 0) {
        float tt = (lane < 8) ? red[lane] : 0.f;
        #pragma unroll
        for (int o = 4; o; o >>= 1) tt += __shfl_xor_sync(0xffffffffu, tt, o);
        if (lane == 0) red[0] = tt;
    }
    __syncthreads();
    float invs = 1.0f / red[0];

    uint4 o0, o1;
    o0.x = f2tf(x[0] * invs); o0.y = f2tf(x[1] * invs);
    o0.z = f2tf(x[2] * invs); o0.w = f2tf(x[3] * invs);
    o1.x = f2tf(x[4] * invs); o1.y = f2tf(x[5] * invs);
    o1.z = f2tf(x[6] * invs); o1.w = f2tf(x[7] * invs);
    *(uint4*)(p + base)     = o0;
    *(uint4*)(p + base + 4) = o1;
}

// ---------------------------------------------------------------------------
// Kernel 5: ctx per batch.  O[2048,1024] = P[2048,2048] @ V[2048,1024]  (NN)
// grid = (8, 16, B); writes directly into d_out.
// ---------------------------------------------------------------------------
__global__ __launch_bounds__(256, 2) void ctx_gemm(float* __restrict__ outp)
{
    extern __shared__ __align__(16) uint32_t smem[];
    uint32_t* As = smem;
    uint32_t* Bs = smem + 2 * ASZ;

    int b = blockIdx.z;
    const float* A  = g_P + (size_t)b * S_ * S_;
    const float* Bm = g_V + (size_t)b * S_ * H_;
    float* out = outp + (size_t)b * S_ * H_;

    int m0 = blockIdx.y * 128, n0 = blockIdx.x * 128;
    float acc[4][4][4] = {};

    gemm_pipe<1>(A, S_, Bm, H_, m0, n0, S_, As, Bs, acc);

    int lane = threadIdx.x & 31, w = threadIdx.x >> 5;
    int g = lane >> 2, t = lane & 3;
    int wm = (w >> 2) * 64, wn = (w & 3) * 32;

    #pragma unroll
    for (int mi = 0; mi < 4; mi++) {
        int row = m0 + wm + 16 * mi + g;
        #pragma unroll
        for (int ni = 0; ni < 4; ni++) {
            int col = n0 + wn + 8 * ni + 2 * t;
            *(float2*)(out + (size_t)row * H_ + col) =
                make_float2(acc[mi][ni][0], acc[mi][ni][1]);
            *(float2*)(out + (size_t)(row + 8) * H_ + col) =
                make_float2(acc[mi][ni][2], acc[mi][ni][3]);
        }
    }
}

// ---------------------------------------------------------------------------
extern "C" void kernel_launch(void* const* d_in, const int* in_sizes, int n_in,
                              void* d_out, int out_size)
{
    const float* hs   = (const float*)d_in[0];
    const float* mask = (const float*)d_in[1];
    const int*   rel  = (const int*)  d_in[2];
    const float* Wq   = (const float*)d_in[3];
    const float* bq   = (const float*)d_in[4];
    const float* Wk   = (const float*)d_in[5];
    const float* bk   = (const float*)d_in[6];
    const float* Wv   = (const float*)d_in[7];
    const float* bv   = (const float*)d_in[8];
    const float* dist = (const float*)d_in[9];

    static bool attr_done = false;
    if (!attr_done) {
        cudaFuncSetAttribute(qkv_gemm,    cudaFuncAttributeMaxDynamicSharedMemorySize, SMEM_TN);
        cudaFuncSetAttribute(scores_gemm, cudaFuncAttributeMaxDynamicSharedMemorySize, SMEM_TN);
        cudaFuncSetAttribute(ctx_gemm,    cudaFuncAttributeMaxDynamicSharedMemorySize, SMEM_NN);
        attr_done = true;
    }

    float* hs_r = nullptr; float* w_r = nullptr;
    cudaGetSymbolAddress((void**)&hs_r, g_HS);
    cudaGetSymbolAddress((void**)&w_r,  g_W);

    dim3 blk(256);
    // tf32 pre-round of raw inputs
    round_tf32_kernel<<<(size_t)M_ * H_ / 1024, blk>>>(hs, hs_r);
    round_tf32_kernel<<<(size_t)H_ * H_ / 1024, blk>>>(Wq, w_r);
    round_tf32_kernel<<<(size_t)H_ * H_ / 1024, blk>>>(Wk, w_r + (size_t)H_ * H_);
    round_tf32_kernel<<<(size_t)H_ * H_ / 1024, blk>>>(Wv, w_r + (size_t)2 * H_ * H_);

    qkv_gemm<<<dim3(H_ / 128, M_ / 128, 3), blk, SMEM_TN>>>(bq, bk, bv);
    d1_kernel<<<M_ / 8, blk>>>(dist);
    scores_gemm<<<dim3(S_ / 128, S_ / 128, B_), blk, SMEM_TN>>>(rel, mask);
    softmax_k<<<M_, blk>>>();
    ctx_gemm<<<dim3(H_ / 128, S_ / 128, B_), blk, SMEM_NN>>>((float*)d_out);
}

// round 13
// speedup vs baseline: 1.0810x; 1.0810x over previous
#include <cuda_runtime.h>
#include <cstdint>

#define B_ 8
#define S_ 2048
#define H_ 1024
#define M_ (B_ * S_)   // 16384

// Scratch (static __device__ — allocation-free per harness rules)
static __device__ float g_Q[(size_t)B_ * S_ * H_];    // 64 MB (tf32-rounded)
static __device__ float g_K[(size_t)B_ * S_ * H_];    // 64 MB (tf32-rounded)
static __device__ float g_V[(size_t)B_ * S_ * H_];    // 64 MB (tf32-rounded)
static __device__ float g_P[(size_t)B_ * S_ * S_];    // 128 MB (scores fp32 -> probs tf32)
static __device__ float g_d1[(size_t)B_ * S_];
static __device__ float g_HS[(size_t)B_ * S_ * H_];   // 64 MB tf32-rounded hidden_states
static __device__ float g_W[(size_t)3 * H_ * H_];     // 12 MB tf32-rounded Wq|Wk|Wv

// ---------------------------------------------------------------------------
// TF32 / cp.async / ldmatrix helpers
// ---------------------------------------------------------------------------
__device__ __forceinline__ uint32_t f2tf(float x) {
    uint32_t u;
    asm("cvt.rna.tf32.f32 %0, %1;" : "=r"(u) : "f"(x));
    return u;
}

__device__ __forceinline__ void mma_tf32(float c[4], const uint32_t a[4], const uint32_t b[2]) {
    asm volatile(
        "mma.sync.aligned.m16n8k8.row.col.f32.tf32.tf32.f32 "
        "{%0,%1,%2,%3}, {%4,%5,%6,%7}, {%8,%9}, {%0,%1,%2,%3};"
        : "+f"(c[0]), "+f"(c[1]), "+f"(c[2]), "+f"(c[3])
        : "r"(a[0]), "r"(a[1]), "r"(a[2]), "r"(a[3]), "r"(b[0]), "r"(b[1]));
}

__device__ __forceinline__ void ldsm_x4(uint32_t r[4], uint32_t addr) {
    asm volatile("ldmatrix.sync.aligned.m8n8.x4.shared.b16 {%0,%1,%2,%3}, [%4];"
        : "=r"(r[0]), "=r"(r[1]), "=r"(r[2]), "=r"(r[3]) : "r"(addr));
}

__device__ __forceinline__ void cp_async16(uint32_t smem_dst, const void* gsrc) {
    asm volatile("cp.async.cg.shared.global [%0], [%1], 16;\n" :: "r"(smem_dst), "l"(gsrc));
}
__device__ __forceinline__ void cp_commit() {
    asm volatile("cp.async.commit_group;\n" ::: "memory");
}
__device__ __forceinline__ void cp_wait1() {
    asm volatile("cp.async.wait_group 1;\n" ::: "memory");
}
__device__ __forceinline__ void cp_wait0() {
    asm volatile("cp.async.wait_group 0;\n" ::: "memory");
}

// ---------------------------------------------------------------------------
// Elementwise tf32 pre-round: dst[i] = round_tf32(src[i])
// ---------------------------------------------------------------------------
__global__ __launch_bounds__(256) void round_tf32_kernel(
    const float* __restrict__ src, float* __restrict__ dst)
{
    size_t i = ((size_t)blockIdx.x * 256 + threadIdx.x) * 4;
    float4 v = *(const float4*)(src + i);
    uint4 u = make_uint4(f2tf(v.x), f2tf(v.y), f2tf(v.z), f2tf(v.w));
    *(uint4*)(dst + i) = u;
}

// ---------------------------------------------------------------------------
// Pipelined GEMM mainloop (tf32 mma.sync + ldmatrix, cp.async double buffer).
// C[128x128] tile = A[m0:,k] * B.  Inputs pre-rounded to tf32 bits.
//   BMODE 0: Bsrc is [N,K] row-major, staged Bs[n][k] pitch 36, ldmatrix frags
//   BMODE 1: Bsrc is [K,N] row-major, staged Bs[k][n] pitch 136, scalar frags
// 256 threads = 8 warps (2x4); warp tile 64x32; mma m16n8k8.
// ---------------------------------------------------------------------------
#define APITCH 36
#define ASZ (128 * APITCH)            // uint32 per A buffer
#define BSZ0 (128 * 36)
#define BSZ1 (32 * 136)

template<int BMODE>
__device__ __forceinline__ void gemm_pipe(
    const float* __restrict__ A, int lda,
    const float* __restrict__ Bsrc, int ldb,
    int m0, int n0, int K,
    uint32_t* As, uint32_t* Bs,
    float acc[4][4][4])
{
    const int BSZ = (BMODE == 0) ? BSZ0 : BSZ1;
    const uint32_t As_s = (uint32_t)__cvta_generic_to_shared(As);
    const uint32_t Bs_s = (uint32_t)__cvta_generic_to_shared(Bs);

    const int tid  = threadIdx.x;
    const int lane = tid & 31;
    const int w    = tid >> 5;
    const int g    = lane >> 2;
    const int t    = lane & 3;
    const int wm   = (w >> 2) * 64;
    const int wn   = (w & 3)  * 32;

    // ldmatrix per-lane source coordinates
    const int lrow = ((lane >> 3) & 1) * 8 + (lane & 7);   // A row within 16
    const int lk   = (lane >> 4) * 4;                      // A k offset within 8
    const int brow = ((lane >> 4) & 1) * 8 + (lane & 7);   // B n row within 16
    const int bk   = ((lane >> 3) & 1) * 4;                // B k offset within 8

    // Per-thread staging coordinates (4 chunks of 16B each for A and B)
    const int ar = tid >> 3, ac = (tid & 7) * 4;          // +32 rows per chunk
    const int br1 = tid >> 5, bc1 = (tid & 31) * 4;       // BMODE1: +8 rows per chunk

    auto stage = [&](int buf, int k0) {
        #pragma unroll
        for (int p = 0; p < 4; p++) {
            int r = ar + p * 32;
            cp_async16(As_s + (uint32_t)(buf * ASZ + r * APITCH + ac) * 4,
                       A + (size_t)(m0 + r) * lda + k0 + ac);
        }
        if (BMODE == 0) {
            #pragma unroll
            for (int p = 0; p < 4; p++) {
                int r = ar + p * 32;
                cp_async16(Bs_s + (uint32_t)(buf * BSZ0 + r * 36 + ac) * 4,
                           Bsrc + (size_t)(n0 + r) * ldb + k0 + ac);
            }
        } else {
            #pragma unroll
            for (int p = 0; p < 4; p++) {
                int r = br1 + p * 8;
                cp_async16(Bs_s + (uint32_t)(buf * BSZ1 + r * 136 + bc1) * 4,
                           Bsrc + (size_t)(k0 + r) * ldb + n0 + bc1);
            }
        }
        cp_commit();
    };

    stage(0, 0);
    int buf = 0;
    for (int k0 = 0; k0 < K; k0 += 32) {
        if (k0 + 32 < K) { stage(buf ^ 1, k0 + 32); cp_wait1(); }
        else             { cp_wait0(); }
        __syncthreads();

        const uint32_t Ab = As_s + (uint32_t)(buf * ASZ) * 4;
        const uint32_t Bb = Bs_s + (uint32_t)(buf * BSZ) * 4;

        #pragma unroll
        for (int ks = 0; ks < 32; ks += 8) {
            uint32_t af[4][4], bf[4][2];
            #pragma unroll
            for (int mi = 0; mi < 4; mi++)
                ldsm_x4(af[mi], Ab + (uint32_t)((wm + 16 * mi + lrow) * APITCH + ks + lk) * 4);
            if (BMODE == 0) {
                #pragma unroll
                for (int p = 0; p < 2; p++) {
                    uint32_t t4[4];
                    ldsm_x4(t4, Bb + (uint32_t)((wn + 16 * p + brow) * 36 + ks + bk) * 4);
                    bf[2 * p][0]     = t4[0];
                    bf[2 * p][1]     = t4[1];
                    bf[2 * p + 1][0] = t4[2];
                    bf[2 * p + 1][1] = t4[3];
                }
            } else {
                const uint32_t* Bp = Bs + buf * BSZ;
                #pragma unroll
                for (int ni = 0; ni < 4; ni++) {
                    const uint32_t* bp = Bp + (ks + t) * 136 + wn + 8 * ni + g;
                    bf[ni][0] = bp[0];
                    bf[ni][1] = bp[4 * 136];
                }
            }
            #pragma unroll
            for (int mi = 0; mi < 4; mi++)
                #pragma unroll
                for (int ni = 0; ni < 4; ni++)
                    mma_tf32(acc[mi][ni], af[mi], bf[ni]);
        }
        __syncthreads();
        buf ^= 1;
    }
}

// Shared-memory footprints
#define SMEM_TN  ((2 * ASZ + 2 * BSZ0) * 4)   // 73728 B (qkv, scores)
#define SMEM_NN  ((2 * ASZ + 2 * BSZ1) * 4)   // 71680 B (ctx)

// ---------------------------------------------------------------------------
// Kernel 1: QKV projections.  C[M,N] = HS[M,K] @ W[N,K]^T + bias
// grid = (H/128, M/128, 3); writes tf32-rounded Q/K/V.
// ---------------------------------------------------------------------------
__global__ __launch_bounds__(256, 2) void qkv_gemm(
    const float* __restrict__ bq, const float* __restrict__ bk,
    const float* __restrict__ bv)
{
    extern __shared__ __align__(16) uint32_t smem[];
    uint32_t* As = smem;
    uint32_t* Bs = smem + 2 * ASZ;

    int z = blockIdx.z;
    const float* W = g_W + (size_t)z * H_ * H_;
    const float* bias = (z == 0) ? bq : (z == 1) ? bk : bv;
    float* out = (z == 0) ? g_Q : (z == 1) ? g_K : g_V;

    int m0 = blockIdx.y * 128, n0 = blockIdx.x * 128;
    float acc[4][4][4] = {};

    gemm_pipe<0>(g_HS, H_, W, H_, m0, n0, H_, As, Bs, acc);

    int lane = threadIdx.x & 31, w = threadIdx.x >> 5;
    int g = lane >> 2, t = lane & 3;
    int wm = (w >> 2) * 64, wn = (w & 3) * 32;

    #pragma unroll
    for (int mi = 0; mi < 4; mi++) {
        int row = m0 + wm + 16 * mi + g;
        #pragma unroll
        for (int ni = 0; ni < 4; ni++) {
            int col = n0 + wn + 8 * ni + 2 * t;
            float b0 = bias[col], b1 = bias[col + 1];
            uint2 lo = make_uint2(f2tf(acc[mi][ni][0] + b0), f2tf(acc[mi][ni][1] + b1));
            uint2 hi = make_uint2(f2tf(acc[mi][ni][2] + b0), f2tf(acc[mi][ni][3] + b1));
            *(uint2*)(out + (size_t)row * H_ + col)       = lo;
            *(uint2*)(out + (size_t)(row + 8) * H_ + col) = hi;
        }
    }
}

// ---------------------------------------------------------------------------
// Kernel 2: d1[b,q] = Q[b,q,:] . dist_emb[1,:]   (one warp per row)
// ---------------------------------------------------------------------------
__global__ __launch_bounds__(256) void d1_kernel(const float* __restrict__ dist)
{
    int row  = blockIdx.x * 8 + (threadIdx.x >> 5);
    int lane = threadIdx.x & 31;
    const float4* q4 = (const float4*)(g_Q + (size_t)row * H_);
    const float4* e4 = (const float4*)(dist + H_);   // row 1 of dist_emb
    float s = 0.f;
    #pragma unroll
    for (int i = lane; i < H_ / 4; i += 32) {
        float4 a = q4[i], b = e4[i];
        s += a.x * b.x + a.y * b.y + a.z * b.z + a.w * b.w;
    }
    #pragma unroll
    for (int o = 16; o; o >>= 1) s += __shfl_xor_sync(0xffffffffu, s, o);
    if (lane == 0) g_d1[row] = s;
}

// ---------------------------------------------------------------------------
// Kernel 3: scores per batch.  S = (Q @ K^T + d1*[rel==1]) / 32 + mask
// grid = (16, 16, B)
// ---------------------------------------------------------------------------
__global__ __launch_bounds__(256, 2) void scores_gemm(
    const int* __restrict__ rel, const float* __restrict__ mask)
{
    extern __shared__ __align__(16) uint32_t smem[];
    uint32_t* As = smem;
    uint32_t* Bs = smem + 2 * ASZ;

    int b = blockIdx.z;
    const float* A  = g_Q + (size_t)b * S_ * H_;
    const float* Bt = g_K + (size_t)b * S_ * H_;
    float* out         = g_P + (size_t)b * S_ * S_;
    const int* relb    = rel + (size_t)b * S_ * S_;
    const float* maskb = mask + (size_t)b * S_;

    int m0 = blockIdx.y * 128, n0 = blockIdx.x * 128;
    float acc[4][4][4] = {};

    gemm_pipe<0>(A, H_, Bt, H_, m0, n0, H_, As, Bs, acc);

    const float inv = 0.03125f;   // 1/sqrt(1024)
    int lane = threadIdx.x & 31, w = threadIdx.x >> 5;
    int g = lane >> 2, t = lane & 3;
    int wm = (w >> 2) * 64, wn = (w & 3) * 32;

    #pragma unroll
    for (int mi = 0; mi < 4; mi++) {
        int row = m0 + wm + 16 * mi + g;
        float dlo = g_d1[(size_t)b * S_ + row];
        float dhi = g_d1[(size_t)b * S_ + row + 8];
        #pragma unroll
        for (int ni = 0; ni < 4; ni++) {
            int col = n0 + wn + 8 * ni + 2 * t;
            float mk0 = maskb[col], mk1 = maskb[col + 1];
            int2 rlo = *(const int2*)(relb + (size_t)row * S_ + col);
            int2 rhi = *(const int2*)(relb + (size_t)(row + 8) * S_ + col);
            float o0 = (acc[mi][ni][0] + (rlo.x == 1 ? dlo : 0.f)) * inv + mk0;
            float o1 = (acc[mi][ni][1] + (rlo.y == 1 ? dlo : 0.f)) * inv + mk1;
            float o2 = (acc[mi][ni][2] + (rhi.x == 1 ? dhi : 0.f)) * inv + mk0;
            float o3 = (acc[mi][ni][3] + (rhi.y == 1 ? dhi : 0.f)) * inv + mk1;
            *(float2*)(out + (size_t)row * S_ + col)       = make_float2(o0, o1);
            *(float2*)(out + (size_t)(row + 8) * S_ + col) = make_float2(o2, o3);
        }
    }
}

// ---------------------------------------------------------------------------
// Kernel 4: row softmax over k (length 2048), in place on g_P.
// Writes tf32-rounded probs (same rounding the GEMM would apply anyway).
// ---------------------------------------------------------------------------
__global__ __launch_bounds__(256) void softmax_k()
{
    __shared__ float red[32];
    int row = blockIdx.x;
    float* p = g_P + (size_t)row * S_;
    int base = threadIdx.x * 8;

    float4 v0 = *(float4*)(p + base);
    float4 v1 = *(float4*)(p + base + 4);
    float x[8] = {v0.x,v0.y,v0.z,v0.w,v1.x,v1.y,v1.z,v1.w};

    float mx = x[0];
    #pragma unroll
    for (int i = 1; i < 8; i++) mx = fmaxf(mx, x[i]);
    #pragma unroll
    for (int o = 16; o; o >>= 1) mx = fmaxf(mx, __shfl_xor_sync(0xffffffffu, mx, o));
    int lane = threadIdx.x & 31, wid = threadIdx.x >> 5;
    if (lane == 0) red[wid] = mx;
    __syncthreads();
    if (wid == 0) {
        float m = (lane < 8) ? red[lane] : -1e30f;
        #pragma unroll
        for (int o = 4; o; o >>= 1) m = fmaxf(m, __shfl_xor_sync(0xffffffffu, m, o));
        if (lane == 0) red[0] = m;
    }
    __syncthreads();
    float m = red[0];

    float s = 0.f;
    #pragma unroll
    for (int i = 0; i < 8; i++) { x[i] = __expf(x[i] - m); s += x[i]; }
    #pragma unroll
    for (int o = 16; o; o >>= 1) s += __shfl_xor_sync(0xffffffffu, s, o);
    __syncthreads();
    if (lane == 0) red[wid] = s;
    __syncthreads();
    if (wid == 0) {
        float tt = (lane < 8) ? red[lane] : 0.f;
        #pragma unroll
        for (int o = 4; o; o >>= 1) tt += __shfl_xor_sync(0xffffffffu, tt, o);
        if (lane == 0) red[0] = tt;
    }
    __syncthreads();
    float invs = 1.0f / red[0];

    uint4 o0, o1;
    o0.x = f2tf(x[0] * invs); o0.y = f2tf(x[1] * invs);
    o0.z = f2tf(x[2] * invs); o0.w = f2tf(x[3] * invs);
    o1.x = f2tf(x[4] * invs); o1.y = f2tf(x[5] * invs);
    o1.z = f2tf(x[6] * invs); o1.w = f2tf(x[7] * invs);
    *(uint4*)(p + base)     = o0;
    *(uint4*)(p + base + 4) = o1;
}

// ---------------------------------------------------------------------------
// Kernel 5: ctx per batch.  O[2048,1024] = P[2048,2048] @ V[2048,1024]  (NN)
// grid = (8, 16, B); writes directly into d_out.
// ---------------------------------------------------------------------------
__global__ __launch_bounds__(256, 2) void ctx_gemm(float* __restrict__ outp)
{
    extern __shared__ __align__(16) uint32_t smem[];
    uint32_t* As = smem;
    uint32_t* Bs = smem + 2 * ASZ;

    int b = blockIdx.z;
    const float* A  = g_P + (size_t)b * S_ * S_;
    const float* Bm = g_V + (size_t)b * S_ * H_;
    float* out = outp + (size_t)b * S_ * H_;

    int m0 = blockIdx.y * 128, n0 = blockIdx.x * 128;
    float acc[4][4][4] = {};

    gemm_pipe<1>(A, S_, Bm, H_, m0, n0, S_, As, Bs, acc);

    int lane = threadIdx.x & 31, w = threadIdx.x >> 5;
    int g = lane >> 2, t = lane & 3;
    int wm = (w >> 2) * 64, wn = (w & 3) * 32;

    #pragma unroll
    for (int mi = 0; mi < 4; mi++) {
        int row = m0 + wm + 16 * mi + g;
        #pragma unroll
        for (int ni = 0; ni < 4; ni++) {
            int col = n0 + wn + 8 * ni + 2 * t;
            *(float2*)(out + (size_t)row * H_ + col) =
                make_float2(acc[mi][ni][0], acc[mi][ni][1]);
            *(float2*)(out + (size_t)(row + 8) * H_ + col) =
                make_float2(acc[mi][ni][2], acc[mi][ni][3]);
        }
    }
}

// ---------------------------------------------------------------------------
extern "C" void kernel_launch(void* const* d_in, const int* in_sizes, int n_in,
                              void* d_out, int out_size)
{
    const float* hs   = (const float*)d_in[0];
    const float* mask = (const float*)d_in[1];
    const int*   rel  = (const int*)  d_in[2];
    const float* Wq   = (const float*)d_in[3];
    const float* bq   = (const float*)d_in[4];
    const float* Wk   = (const float*)d_in[5];
    const float* bk   = (const float*)d_in[6];
    const float* Wv   = (const float*)d_in[7];
    const float* bv   = (const float*)d_in[8];
    const float* dist = (const float*)d_in[9];

    static bool attr_done = false;
    if (!attr_done) {
        cudaFuncSetAttribute(qkv_gemm,    cudaFuncAttributeMaxDynamicSharedMemorySize, SMEM_TN);
        cudaFuncSetAttribute(scores_gemm, cudaFuncAttributeMaxDynamicSharedMemorySize, SMEM_TN);
        cudaFuncSetAttribute(ctx_gemm,    cudaFuncAttributeMaxDynamicSharedMemorySize, SMEM_NN);
        attr_done = true;
    }

    float* hs_r = nullptr; float* w_r = nullptr;
    cudaGetSymbolAddress((void**)&hs_r, g_HS);
    cudaGetSymbolAddress((void**)&w_r,  g_W);

    dim3 blk(256);
    // tf32 pre-round of raw inputs
    round_tf32_kernel<<<(size_t)M_ * H_ / 1024, blk>>>(hs, hs_r);
    round_tf32_kernel<<<(size_t)H_ * H_ / 1024, blk>>>(Wq, w_r);
    round_tf32_kernel<<<(size_t)H_ * H_ / 1024, blk>>>(Wk, w_r + (size_t)H_ * H_);
    round_tf32_kernel<<<(size_t)H_ * H_ / 1024, blk>>>(Wv, w_r + (size_t)2 * H_ * H_);

    qkv_gemm<<<dim3(H_ / 128, M_ / 128, 3), blk, SMEM_TN>>>(bq, bk, bv);
    d1_kernel<<<M_ / 8, blk>>>(dist);
    scores_gemm<<<dim3(S_ / 128, S_ / 128, B_), blk, SMEM_TN>>>(rel, mask);
    softmax_k<<<M_, blk>>>();
    ctx_gemm<<<dim3(H_ / 128, S_ / 128, B_), blk, SMEM_NN>>>((float*)d_out);
}

// round 14
// speedup vs baseline: 1.8375x; 1.6999x over previous
#include <cuda_runtime.h>
#include <cuda_fp16.h>
#include <cstdint>

#define B_ 8
#define S_ 2048
#define H_ 1024
#define M_ (B_ * S_)   // 16384

// Scratch (static __device__ — allocation-free per harness rules)
static __device__ __half g_Q [(size_t)B_ * S_ * H_];   // 32 MB fp16
static __device__ __half g_K [(size_t)B_ * S_ * H_];   // 32 MB fp16
static __device__ __half g_V [(size_t)B_ * S_ * H_];   // 32 MB fp16
static __device__ float  g_P [(size_t)B_ * S_ * S_];   // 128 MB scores fp32
static __device__ __half g_Ph[(size_t)B_ * S_ * S_];   // 64 MB probs fp16
static __device__ float  g_d1[(size_t)B_ * S_];
static __device__ __half g_HS[(size_t)B_ * S_ * H_];   // 32 MB fp16 hidden_states
static __device__ __half g_W [(size_t)3 * H_ * H_];    // 6 MB fp16 Wq|Wk|Wv

// ---------------------------------------------------------------------------
// helpers
// ---------------------------------------------------------------------------
__device__ __forceinline__ void mma_f16(float c[4], const uint32_t a[4], const uint32_t b[2]) {
    asm volatile(
        "mma.sync.aligned.m16n8k16.row.col.f32.f16.f16.f32 "
        "{%0,%1,%2,%3}, {%4,%5,%6,%7}, {%8,%9}, {%0,%1,%2,%3};"
        : "+f"(c[0]), "+f"(c[1]), "+f"(c[2]), "+f"(c[3])
        : "r"(a[0]), "r"(a[1]), "r"(a[2]), "r"(a[3]), "r"(b[0]), "r"(b[1]));
}
__device__ __forceinline__ void ldsm_x4(uint32_t r[4], uint32_t addr) {
    asm volatile("ldmatrix.sync.aligned.m8n8.x4.shared.b16 {%0,%1,%2,%3}, [%4];"
        : "=r"(r[0]), "=r"(r[1]), "=r"(r[2]), "=r"(r[3]) : "r"(addr));
}
__device__ __forceinline__ void ldsm_x4_t(uint32_t r[4], uint32_t addr) {
    asm volatile("ldmatrix.sync.aligned.m8n8.x4.trans.shared.b16 {%0,%1,%2,%3}, [%4];"
        : "=r"(r[0]), "=r"(r[1]), "=r"(r[2]), "=r"(r[3]) : "r"(addr));
}
__device__ __forceinline__ void cp_async16(uint32_t smem_dst, const void* gsrc) {
    asm volatile("cp.async.cg.shared.global [%0], [%1], 16;\n" :: "r"(smem_dst), "l"(gsrc));
}
__device__ __forceinline__ void cp_commit() {
    asm volatile("cp.async.commit_group;\n" ::: "memory");
}
__device__ __forceinline__ void cp_wait1() {
    asm volatile("cp.async.wait_group 1;\n" ::: "memory");
}
__device__ __forceinline__ void cp_wait0() {
    asm volatile("cp.async.wait_group 0;\n" ::: "memory");
}
__device__ __forceinline__ uint32_t pack_h2(float a, float b) {
    __half2 h = __float22half2_rn(make_float2(a, b));
    return *(uint32_t*)&h;
}

// ---------------------------------------------------------------------------
// Elementwise fp32 -> fp16 pre-round (8 elems/thread)
// ---------------------------------------------------------------------------
__global__ __launch_bounds__(256) void round_f16_kernel(
    const float* __restrict__ src, __half* __restrict__ dst)
{
    size_t i = ((size_t)blockIdx.x * 256 + threadIdx.x) * 8;
    float4 a = *(const float4*)(src + i);
    float4 b = *(const float4*)(src + i + 4);
    uint4 u;
    u.x = pack_h2(a.x, a.y); u.y = pack_h2(a.z, a.w);
    u.z = pack_h2(b.x, b.y); u.w = pack_h2(b.z, b.w);
    *(uint4*)(dst + i) = u;
}

// ---------------------------------------------------------------------------
// Pipelined fp16 GEMM mainloop (mma.sync m16n8k16 + ldmatrix, cp.async 2-buf).
// C[128x128] tile = A[m0:,k] * B.
//   BMODE 0: Bsrc [N,K] row-major, staged Bs[n][k] pitch 72, ldmatrix frags
//   BMODE 1: Bsrc [K,N] row-major, staged Bs[k][n] pitch 136, ldmatrix.trans
// 256 threads = 8 warps (2x4); warp tile 64x32; KC=64 halves per stage.
// Pitches: 72h=144B=9x16B -> bank-group (9r)%8 distinct; 136h=272B=17x16B ok.
// ---------------------------------------------------------------------------
#define APITCH 72
#define ASZ (128 * APITCH)            // halves per A stage buffer
#define BSZ0 (128 * 72)
#define BSZ1 (64 * 136)

template<int BMODE>
__device__ __forceinline__ void gemm_pipe(
    const __half* __restrict__ A, int lda,
    const __half* __restrict__ Bsrc, int ldb,
    int m0, int n0, int K,
    __half* As, __half* Bs,
    float acc[4][4][4])
{
    const int BSZ = (BMODE == 0) ? BSZ0 : BSZ1;
    const uint32_t As_s = (uint32_t)__cvta_generic_to_shared(As);
    const uint32_t Bs_s = (uint32_t)__cvta_generic_to_shared(Bs);

    const int tid  = threadIdx.x;
    const int lane = tid & 31;
    const int w    = tid >> 5;
    const int wm   = (w >> 2) * 64;
    const int wn   = (w & 3)  * 32;

    // ldmatrix lane coords
    const int lrow = lane & 15;            // row within 16
    const int lc8  = (lane >> 4) * 8;      // 8-half column chunk
    const int tkoff = ((lane >> 3) & 1) * 8 + (lane & 7);  // trans: k row
    const int tnoff = (lane >> 4) * 8;                     // trans: n col

    // staging coords
    const int ar = tid >> 3, ac = (tid & 7) * 8;     // A/B0: 8 chunks/row
    const int br1 = tid >> 4, bc1 = (tid & 15) * 8;  // B1: 16 chunks/row

    auto stage = [&](int buf, int k0) {
        #pragma unroll
        for (int p = 0; p < 4; p++) {
            int r = ar + p * 32;
            cp_async16(As_s + (uint32_t)(buf * ASZ + r * APITCH + ac) * 2,
                       A + (size_t)(m0 + r) * lda + k0 + ac);
        }
        if (BMODE == 0) {
            #pragma unroll
            for (int p = 0; p < 4; p++) {
                int r = ar + p * 32;
                cp_async16(Bs_s + (uint32_t)(buf * BSZ0 + r * 72 + ac) * 2,
                           Bsrc + (size_t)(n0 + r) * ldb + k0 + ac);
            }
        } else {
            #pragma unroll
            for (int p = 0; p < 4; p++) {
                int r = br1 + p * 16;
                cp_async16(Bs_s + (uint32_t)(buf * BSZ1 + r * 136 + bc1) * 2,
                           Bsrc + (size_t)(k0 + r) * ldb + n0 + bc1);
            }
        }
        cp_commit();
    };

    stage(0, 0);
    int buf = 0;
    for (int k0 = 0; k0 < K; k0 += 64) {
        if (k0 + 64 < K) { stage(buf ^ 1, k0 + 64); cp_wait1(); }
        else             { cp_wait0(); }
        __syncthreads();

        const uint32_t Ab = As_s + (uint32_t)(buf * ASZ) * 2;
        const uint32_t Bb = Bs_s + (uint32_t)(buf * BSZ) * 2;

        #pragma unroll
        for (int ks = 0; ks < 4; ks++) {             // 4 x k16
            uint32_t af[4][4], bf[4][2];
            #pragma unroll
            for (int mi = 0; mi < 4; mi++)
                ldsm_x4(af[mi], Ab + (uint32_t)((wm + 16 * mi + lrow) * APITCH
                                                + ks * 16 + lc8) * 2);
            if (BMODE == 0) {
                #pragma unroll
                for (int p = 0; p < 2; p++) {
                    uint32_t t4[4];
                    ldsm_x4(t4, Bb + (uint32_t)((wn + 16 * p + lrow) * 72
                                                + ks * 16 + lc8) * 2);
                    bf[2 * p][0]     = t4[0];   // (n0-7 , k0-7 )
                    bf[2 * p + 1][0] = t4[1];   // (n8-15, k0-7 )
                    bf[2 * p][1]     = t4[2];   // (n0-7 , k8-15)
                    bf[2 * p + 1][1] = t4[3];   // (n8-15, k8-15)
                }
            } else {
                #pragma unroll
                for (int p = 0; p < 2; p++) {
                    uint32_t t4[4];
                    ldsm_x4_t(t4, Bb + (uint32_t)((ks * 16 + tkoff) * 136
                                                  + wn + 16 * p + tnoff) * 2);
                    bf[2 * p][0]     = t4[0];   // (k0-7 , n0-7 )
                    bf[2 * p][1]     = t4[1];   // (k8-15, n0-7 )
                    bf[2 * p + 1][0] = t4[2];   // (k0-7 , n8-15)
                    bf[2 * p + 1][1] = t4[3];   // (k8-15, n8-15)
                }
            }
            #pragma unroll
            for (int mi = 0; mi < 4; mi++)
                #pragma unroll
                for (int ni = 0; ni < 4; ni++)
                    mma_f16(acc[mi][ni], af[mi], bf[ni]);
        }
        __syncthreads();
        buf ^= 1;
    }
}

// Shared-memory footprints (bytes)
#define SMEM_TN  ((2 * ASZ + 2 * BSZ0) * 2)   // 73728 B (qkv, scores)
#define SMEM_NN  ((2 * ASZ + 2 * BSZ1) * 2)   // 71680 B (ctx)

// ---------------------------------------------------------------------------
// Kernel 1: QKV projections.  C[M,N] = HS[M,K] @ W[N,K]^T + bias -> fp16
// grid = (H/128, M/128, 3)
// ---------------------------------------------------------------------------
__global__ __launch_bounds__(256, 2) void qkv_gemm(
    const float* __restrict__ bq, const float* __restrict__ bk,
    const float* __restrict__ bv)
{
    extern __shared__ __align__(16) __half smem[];
    __half* As = smem;
    __half* Bs = smem + 2 * ASZ;

    int z = blockIdx.z;
    const __half* W = g_W + (size_t)z * H_ * H_;
    const float* bias = (z == 0) ? bq : (z == 1) ? bk : bv;
    __half* out = (z == 0) ? g_Q : (z == 1) ? g_K : g_V;

    int m0 = blockIdx.y * 128, n0 = blockIdx.x * 128;
    float acc[4][4][4] = {};

    gemm_pipe<0>(g_HS, H_, W, H_, m0, n0, H_, As, Bs, acc);

    int lane = threadIdx.x & 31, w = threadIdx.x >> 5;
    int g = lane >> 2, t = lane & 3;
    int wm = (w >> 2) * 64, wn = (w & 3) * 32;

    #pragma unroll
    for (int mi = 0; mi < 4; mi++) {
        int row = m0 + wm + 16 * mi + g;
        #pragma unroll
        for (int ni = 0; ni < 4; ni++) {
            int col = n0 + wn + 8 * ni + 2 * t;
            float b0 = bias[col], b1 = bias[col + 1];
            *(uint32_t*)(out + (size_t)row * H_ + col) =
                pack_h2(acc[mi][ni][0] + b0, acc[mi][ni][1] + b1);
            *(uint32_t*)(out + (size_t)(row + 8) * H_ + col) =
                pack_h2(acc[mi][ni][2] + b0, acc[mi][ni][3] + b1);
        }
    }
}

// ---------------------------------------------------------------------------
// Kernel 2: d1[b,q] = Q[b,q,:] . dist_emb[1,:]   (one warp per row)
// ---------------------------------------------------------------------------
__global__ __launch_bounds__(256) void d1_kernel(const float* __restrict__ dist)
{
    int row  = blockIdx.x * 8 + (threadIdx.x >> 5);
    int lane = threadIdx.x & 31;
    const __half2* q2 = (const __half2*)(g_Q + (size_t)row * H_);
    const float2*  e2 = (const float2*)(dist + H_);   // row 1 of dist_emb
    float s = 0.f;
    #pragma unroll 4
    for (int i = lane; i < H_ / 2; i += 32) {
        float2 q = __half22float2(q2[i]);
        float2 e = e2[i];
        s += q.x * e.x + q.y * e.y;
    }
    #pragma unroll
    for (int o = 16; o; o >>= 1) s += __shfl_xor_sync(0xffffffffu, s, o);
    if (lane == 0) g_d1[row] = s;
}

// ---------------------------------------------------------------------------
// Kernel 3: scores per batch.  S = (Q @ K^T + d1*[rel==1]) / 32 + mask (fp32)
// grid = (16, 16, B)
// ---------------------------------------------------------------------------
__global__ __launch_bounds__(256, 2) void scores_gemm(
    const int* __restrict__ rel, const float* __restrict__ mask)
{
    extern __shared__ __align__(16) __half smem[];
    __half* As = smem;
    __half* Bs = smem + 2 * ASZ;

    int b = blockIdx.z;
    const __half* A  = g_Q + (size_t)b * S_ * H_;
    const __half* Bt = g_K + (size_t)b * S_ * H_;
    float* out         = g_P + (size_t)b * S_ * S_;
    const int* relb    = rel + (size_t)b * S_ * S_;
    const float* maskb = mask + (size_t)b * S_;

    int m0 = blockIdx.y * 128, n0 = blockIdx.x * 128;
    float acc[4][4][4] = {};

    gemm_pipe<0>(A, H_, Bt, H_, m0, n0, H_, As, Bs, acc);

    const float inv = 0.03125f;   // 1/sqrt(1024)
    int lane = threadIdx.x & 31, w = threadIdx.x >> 5;
    int g = lane >> 2, t = lane & 3;
    int wm = (w >> 2) * 64, wn = (w & 3) * 32;

    #pragma unroll
    for (int mi = 0; mi < 4; mi++) {
        int row = m0 + wm + 16 * mi + g;
        float dlo = g_d1[(size_t)b * S_ + row];
        float dhi = g_d1[(size_t)b * S_ + row + 8];
        #pragma unroll
        for (int ni = 0; ni < 4; ni++) {
            int col = n0 + wn + 8 * ni + 2 * t;
            float mk0 = maskb[col], mk1 = maskb[col + 1];
            int2 rlo = *(const int2*)(relb + (size_t)row * S_ + col);
            int2 rhi = *(const int2*)(relb + (size_t)(row + 8) * S_ + col);
            float o0 = (acc[mi][ni][0] + (rlo.x == 1 ? dlo : 0.f)) * inv + mk0;
            float o1 = (acc[mi][ni][1] + (rlo.y == 1 ? dlo : 0.f)) * inv + mk1;
            float o2 = (acc[mi][ni][2] + (rhi.x == 1 ? dhi : 0.f)) * inv + mk0;
            float o3 = (acc[mi][ni][3] + (rhi.y == 1 ? dhi : 0.f)) * inv + mk1;
            *(float2*)(out + (size_t)row * S_ + col)       = make_float2(o0, o1);
            *(float2*)(out + (size_t)(row + 8) * S_ + col) = make_float2(o2, o3);
        }
    }
}

// ---------------------------------------------------------------------------
// Kernel 4: row softmax over k (2048): read fp32 g_P, write fp16 g_Ph.
// ---------------------------------------------------------------------------
__global__ __launch_bounds__(256) void softmax_k()
{
    __shared__ float red[32];
    int row = blockIdx.x;
    const float* p = g_P  + (size_t)row * S_;
    __half* ph     = g_Ph + (size_t)row * S_;
    int base = threadIdx.x * 8;

    float4 v0 = *(const float4*)(p + base);
    float4 v1 = *(const float4*)(p + base + 4);
    float x[8] = {v0.x,v0.y,v0.z,v0.w,v1.x,v1.y,v1.z,v1.w};

    float mx = x[0];
    #pragma unroll
    for (int i = 1; i < 8; i++) mx = fmaxf(mx, x[i]);
    #pragma unroll
    for (int o = 16; o; o >>= 1) mx = fmaxf(mx, __shfl_xor_sync(0xffffffffu, mx, o));
    int lane = threadIdx.x & 31, wid = threadIdx.x >> 5;
    if (lane == 0) red[wid] = mx;
    __syncthreads();
    if (wid == 0) {
        float m = (lane < 8) ? red[lane] : -1e30f;
        #pragma unroll
        for (int o = 4; o; o >>= 1) m = fmaxf(m, __shfl_xor_sync(0xffffffffu, m, o));
        if (lane == 0) red[0] = m;
    }
    __syncthreads();
    float m = red[0];

    float s = 0.f;
    #pragma unroll
    for (int i = 0; i < 8; i++) { x[i] = __expf(x[i] - m); s += x[i]; }
    #pragma unroll
    for (int o = 16; o; o >>= 1) s += __shfl_xor_sync(0xffffffffu, s, o);
    __syncthreads();
    if (lane == 0) red[wid] = s;
    __syncthreads();
    if (wid == 0) {
        float tt = (lane < 8) ? red[lane] : 0.f;
        #pragma unroll
        for (int o = 4; o; o >>= 1) tt += __shfl_xor_sync(0xffffffffu, tt, o);
        if (lane == 0) red[0] = tt;
    }
    __syncthreads();
    float invs = 1.0f / red[0];

    uint4 u;
    u.x = pack_h2(x[0] * invs, x[1] * invs);
    u.y = pack_h2(x[2] * invs, x[3] * invs);
    u.z = pack_h2(x[4] * invs, x[5] * invs);
    u.w = pack_h2(x[6] * invs, x[7] * invs);
    *(uint4*)(ph + base) = u;
}

// ---------------------------------------------------------------------------
// Kernel 5: ctx per batch.  O[2048,1024] = Ph[2048,2048] @ V[2048,1024] (NN)
// grid = (8, 16, B); writes fp32 directly into d_out.
// ---------------------------------------------------------------------------
__global__ __launch_bounds__(256, 2) void ctx_gemm(float* __restrict__ outp)
{
    extern __shared__ __align__(16) __half smem[];
    __half* As = smem;
    __half* Bs = smem + 2 * ASZ;

    int b = blockIdx.z;
    const __half* A  = g_Ph + (size_t)b * S_ * S_;
    const __half* Bm = g_V  + (size_t)b * S_ * H_;
    float* out = outp + (size_t)b * S_ * H_;

    int m0 = blockIdx.y * 128, n0 = blockIdx.x * 128;
    float acc[4][4][4] = {};

    gemm_pipe<1>(A, S_, Bm, H_, m0, n0, S_, As, Bs, acc);

    int lane = threadIdx.x & 31, w = threadIdx.x >> 5;
    int g = lane >> 2, t = lane & 3;
    int wm = (w >> 2) * 64, wn = (w & 3) * 32;

    #pragma unroll
    for (int mi = 0; mi < 4; mi++) {
        int row = m0 + wm + 16 * mi + g;
        #pragma unroll
        for (int ni = 0; ni < 4; ni++) {
            int col = n0 + wn + 8 * ni + 2 * t;
            *(float2*)(out + (size_t)row * H_ + col) =
                make_float2(acc[mi][ni][0], acc[mi][ni][1]);
            *(float2*)(out + (size_t)(row + 8) * H_ + col) =
                make_float2(acc[mi][ni][2], acc[mi][ni][3]);
        }
    }
}

// ---------------------------------------------------------------------------
extern "C" void kernel_launch(void* const* d_in, const int* in_sizes, int n_in,
                              void* d_out, int out_size)
{
    const float* hs   = (const float*)d_in[0];
    const float* mask = (const float*)d_in[1];
    const int*   rel  = (const int*)  d_in[2];
    const float* Wq   = (const float*)d_in[3];
    const float* bq   = (const float*)d_in[4];
    const float* Wk   = (const float*)d_in[5];
    const float* bk   = (const float*)d_in[6];
    const float* Wv   = (const float*)d_in[7];
    const float* bv   = (const float*)d_in[8];
    const float* dist = (const float*)d_in[9];

    static bool attr_done = false;
    if (!attr_done) {
        cudaFuncSetAttribute(qkv_gemm,    cudaFuncAttributeMaxDynamicSharedMemorySize, SMEM_TN);
        cudaFuncSetAttribute(scores_gemm, cudaFuncAttributeMaxDynamicSharedMemorySize, SMEM_TN);
        cudaFuncSetAttribute(ctx_gemm,    cudaFuncAttributeMaxDynamicSharedMemorySize, SMEM_NN);
        attr_done = true;
    }

    __half* hs_r = nullptr; __half* w_r = nullptr;
    cudaGetSymbolAddress((void**)&hs_r, g_HS);
    cudaGetSymbolAddress((void**)&w_r,  g_W);

    dim3 blk(256);
    // fp16 pre-round of raw inputs (2048 elems per block)
    round_f16_kernel<<<(size_t)M_ * H_ / 2048, blk>>>(hs, hs_r);
    round_f16_kernel<<<(size_t)H_ * H_ / 2048, blk>>>(Wq, w_r);
    round_f16_kernel<<<(size_t)H_ * H_ / 2048, blk>>>(Wk, w_r + (size_t)H_ * H_);
    round_f16_kernel<<<(size_t)H_ * H_ / 2048, blk>>>(Wv, w_r + (size_t)2 * H_ * H_);

    qkv_gemm<<<dim3(H_ / 128, M_ / 128, 3), blk, SMEM_TN>>>(bq, bk, bv);
    d1_kernel<<<M_ / 8, blk>>>(dist);
    scores_gemm<<<dim3(S_ / 128, S_ / 128, B_), blk, SMEM_TN>>>(rel, mask);
    softmax_k<<<M_, blk>>>();
    ctx_gemm<<<dim3(H_ / 128, S_ / 128, B_), blk, SMEM_NN>>>((float*)d_out);
}